// round 1
// baseline (speedup 1.0000x reference)
#include <cuda_runtime.h>
#include <math.h>

// ---------------------------------------------------------------------------
// Pipeline: spectrogram -> bilinear resize -> folded 7x7/s2 conv + ReLU + GAP
//           -> FC.  All scratch in static __device__ arrays (no allocation).
// ---------------------------------------------------------------------------

#define BMAX     256
#define SIGLEN   178
#define STEP     4
#define NFR      43          // time frames
#define NFQ      33          // freq bins (rfft of NFFT=64 -> 33)
#define OHW      178         // resized image H=W
#define COUT     64
#define CONV_OUT 89          // (178+6-7)/2+1
#define ROWS_PER_TILE 8
#define TILES    12          // ceil(89/8)

__device__ float g_spec[BMAX * NFQ * NFR];          // [b][freq][time]
__device__ float g_img [BMAX * OHW * OHW];          // [b][y][x]
__device__ float g_wsum[COUT * 49];                 // channel-folded weights
__device__ float g_partial[BMAX * TILES * COUT];    // per-(b,tile) relu sums

// ---- fold conv weights over the 3 identical input channels ----------------
__global__ void fold_w_kernel(const float* __restrict__ w) {
    int t = blockIdx.x * blockDim.x + threadIdx.x;
    if (t < COUT * 49) {
        int c = t / 49, kk = t % 49;
        const float* p = w + c * 147;   // (64,3,7,7)
        g_wsum[t] = p[kk] + p[49 + kk] + p[98 + kk];
    }
}

// ---- spectrogram: one thread per (b, frame, freq-bin) ----------------------
__global__ void spec_kernel(const float* __restrict__ x, int B) {
    int t = blockIdx.x * blockDim.x + threadIdx.x;
    int total = B * NFR * NFQ;
    if (t >= total) return;
    int k  = t % NFQ;
    int r  = t / NFQ;
    int fr = r % NFR;
    int b  = r / NFR;

    const float* s = x + b * SIGLEN + fr * STEP;
    float v[8];
    float mean = 0.f;
#pragma unroll
    for (int n = 0; n < 8; n++) { v[n] = s[n]; mean += v[n]; }
    mean *= 0.125f;

    // Tukey(8, 0.25, periodic) == [0,1,1,1,1,1,1,1]
    float re = 0.f, im = 0.f;
#pragma unroll
    for (int n = 1; n < 8; n++) {
        float f = v[n] - mean;
        float sn, cs;
        sincospif((float)(k * n) * (1.0f / 32.0f), &sn, &cs);  // 2*pi*k*n/64
        re += f * cs;
        im -= f * sn;
    }
    const float SCALE = sqrtf(1.0f / (178.0f * 7.0f));
    g_spec[b * (NFQ * NFR) + k * NFR + fr] = sqrtf(re * re + im * im) * SCALE;
}

// ---- bilinear resize (33,43) -> (178,178), clamp-to-edge ------------------
__global__ void resize_kernel(int B) {
    int t = blockIdx.x * blockDim.x + threadIdx.x;
    int total = B * OHW * OHW;
    if (t >= total) return;
    int xo = t % OHW;
    int r  = t / OHW;
    int yo = r % OHW;
    int b  = r / OHW;

    float sy = fminf(fmaxf((yo + 0.5f) * (33.0f / 178.0f) - 0.5f, 0.f), 32.0f);
    float sx = fminf(fmaxf((xo + 0.5f) * (43.0f / 178.0f) - 0.5f, 0.f), 42.0f);
    int   y0 = (int)sy;  float fy = sy - (float)y0;  int y1 = min(y0 + 1, 32);
    int   x0 = (int)sx;  float fx = sx - (float)x0;  int x1 = min(x0 + 1, 42);

    const float* sp = g_spec + b * (NFQ * NFR);
    float v00 = sp[y0 * NFR + x0], v01 = sp[y0 * NFR + x1];
    float v10 = sp[y1 * NFR + x0], v11 = sp[y1 * NFR + x1];
    float v0 = v00 + (v01 - v00) * fx;
    float v1 = v10 + (v11 - v10) * fx;
    g_img[t] = v0 + (v1 - v0) * fy;
}

// ---- conv(7x7,s2,p3) + bias + ReLU + spatial partial-sum ------------------
// Block: 256 threads = 64 channels x 4 position-groups. One (batch, row-tile)
// per block. Input tile (21 x 192 padded) in smem; weights in registers;
// 4-wide output-column register blocking (13 smem loads feed 196 FMAs).
#define SPITCH 192
#define SROWS  21

__global__ void __launch_bounds__(256, 2)
conv_reduce_kernel(const float* __restrict__ bias, int B) {
    __shared__ float s_in[SROWS * SPITCH];
    __shared__ float s_sum[256];

    int b    = blockIdx.y;
    int tile = blockIdx.x;
    int r0   = tile * ROWS_PER_TILE;
    int tid  = threadIdx.x;

    int gr0 = 2 * r0 - 3;
    const float* imgb = g_img + b * OHW * OHW;
    for (int idx = tid; idx < SROWS * SPITCH; idx += 256) {
        int row = idx / SPITCH, col = idx % SPITCH;
        int gy = gr0 + row, gx = col - 3;
        float v = 0.f;
        if (gy >= 0 && gy < OHW && gx >= 0 && gx < OHW)
            v = imgb[gy * OHW + gx];
        s_in[idx] = v;
    }
    __syncthreads();

    int c   = tid & 63;
    int grp = tid >> 6;

    float w[49];
#pragma unroll
    for (int kk = 0; kk < 49; kk++) w[kk] = g_wsum[c * 49 + kk];
    float bc = bias[c];

    float sum = 0.f;
    // 23 col-quads per row (88 full + 1 partial handled by predication)
    for (int q = grp; q < ROWS_PER_TILE * 23; q += 4) {
        int rr = q / 23;
        int j0 = (q % 23) * 4;
        int r  = r0 + rr;
        if (r >= CONV_OUT) continue;

        float a0 = 0.f, a1 = 0.f, a2 = 0.f, a3 = 0.f;
#pragma unroll
        for (int ky = 0; ky < 7; ky++) {
            const float* rp = &s_in[(2 * rr + ky) * SPITCH + 2 * j0];
            float xv[13];
#pragma unroll
            for (int i = 0; i < 13; i++) xv[i] = rp[i];
#pragma unroll
            for (int kx = 0; kx < 7; kx++) {
                float wv = w[ky * 7 + kx];
                a0 = fmaf(wv, xv[kx    ], a0);
                a1 = fmaf(wv, xv[kx + 2], a1);
                a2 = fmaf(wv, xv[kx + 4], a2);
                a3 = fmaf(wv, xv[kx + 6], a3);
            }
        }
        sum += fmaxf(a0 + bc, 0.f);
        if (j0 + 1 < CONV_OUT) sum += fmaxf(a1 + bc, 0.f);
        if (j0 + 2 < CONV_OUT) sum += fmaxf(a2 + bc, 0.f);
        if (j0 + 3 < CONV_OUT) sum += fmaxf(a3 + bc, 0.f);
    }

    s_sum[tid] = sum;
    __syncthreads();
    if (grp == 0) {
        float tsum = s_sum[c] + s_sum[c + 64] + s_sum[c + 128] + s_sum[c + 192];
        g_partial[(b * TILES + tile) * COUT + c] = tsum;
    }
}

// ---- final: GAP mean + FC --------------------------------------------------
__global__ void fc_kernel(const float* __restrict__ fw,
                          const float* __restrict__ fb,
                          float* __restrict__ out, int B) {
    int t = blockIdx.x * blockDim.x + threadIdx.x;
    if (t >= B * 5) return;
    int n = t % 5, b = t / 5;
    float acc = fb[n];
    const float inv = 1.0f / (float)(CONV_OUT * CONV_OUT);
#pragma unroll 4
    for (int c = 0; c < COUT; c++) {
        float s = 0.f;
#pragma unroll
        for (int tt = 0; tt < TILES; tt++)
            s += g_partial[(b * TILES + tt) * COUT + c];
        acc = fmaf(s * inv, fw[n * 64 + c], acc);
    }
    out[t] = acc;
}

// ---------------------------------------------------------------------------
extern "C" void kernel_launch(void* const* d_in, const int* in_sizes, int n_in,
                              void* d_out, int out_size) {
    const float* x      = (const float*)d_in[0];   // (B,1,178)
    const float* conv_w = (const float*)d_in[1];   // (64,3,7,7)
    const float* conv_b = (const float*)d_in[2];   // (64,)
    const float* fc_w   = (const float*)d_in[3];   // (5,64)
    const float* fc_b   = (const float*)d_in[4];   // (5,)
    float*       out    = (float*)d_out;           // (B,5)

    int B = in_sizes[0] / SIGLEN;
    if (B > BMAX) B = BMAX;

    fold_w_kernel<<<(COUT * 49 + 255) / 256, 256>>>(conv_w);

    int nspec = B * NFR * NFQ;
    spec_kernel<<<(nspec + 255) / 256, 256>>>(x, B);

    int nimg = B * OHW * OHW;
    resize_kernel<<<(nimg + 255) / 256, 256>>>(B);

    dim3 cgrid(TILES, B);
    conv_reduce_kernel<<<cgrid, 256>>>(conv_b, B);

    fc_kernel<<<(B * 5 + 255) / 256, 256>>>(fc_w, fc_b, out, B);
}

// round 3
// speedup vs baseline: 1.9047x; 1.9047x over previous
#include <cuda_runtime.h>
#include <math.h>

#define BMAX     256
#define SIGLEN   178
#define STEP     4
#define NFR      43          // time frames  (src cols)
#define NFQ      33          // freq bins    (src rows)
#define COUT     64
#define CONV_OUT 89
#define NB       16          // batches per chunk
#define NPARTS   48          // 6 jg * 8 rs

__device__ float g_spec [BMAX * NFQ * NFR];       // [b][p][q]
__device__ float g_wsum [COUT * 49];              // channel-folded 7x7
__device__ float g_phi  [89 * 4 * 7 * 64];        // [j][qt][ky][c]
__device__ float g_theta[89 * 89 * 16 * 64];      // [r][j][tap][c]  (32.4 MB)
__device__ float g_part [BMAX * COUT * NPARTS];

// ---- shared index helpers (MUST match between precompute and main) --------
__device__ __forceinline__ int q0raw(int j) {
    float sx = (2 * j - 3 + 0.5f) * (43.0f / 178.0f) - 0.5f;
    sx = fminf(fmaxf(sx, 0.f), 42.f);
    return (int)sx;
}
__device__ __forceinline__ int q0f(int j) { int q = q0raw(j); return q > 39 ? 39 : q; }
__device__ __forceinline__ int p0f(int r) {
    float sy = (2 * r - 3 + 0.5f) * (33.0f / 178.0f) - 0.5f;
    sy = fminf(fmaxf(sy, 0.f), 32.f);
    int p = (int)sy; return p > 29 ? 29 : p;
}
// bilinear weight of src col q at image col x (0 outside image; clamp-to-edge)
__device__ __forceinline__ float bweight(int x, int q) {
    if (x < 0 || x >= 178) return 0.f;
    float sx = fminf(fmaxf((x + 0.5f) * (43.0f / 178.0f) - 0.5f, 0.f), 42.f);
    int x0 = (int)sx; float fx = sx - (float)x0; int x1 = min(x0 + 1, 42);
    float w = 0.f;
    if (q == x0) w += 1.f - fx;
    if (q == x1) w += fx;
    return w;
}

// ---- packed f32x2 helpers --------------------------------------------------
#define PACK2(d, x)  asm("mov.b64 %0, {%1, %1};" : "=l"(d) : "f"(x))
#define UNPACK2(lo, hi, d) asm("mov.b64 {%0, %1}, %2;" : "=f"(lo), "=f"(hi) : "l"(d))
#define FFMA2(d, a, b) asm("fma.rn.f32x2 %0, %1, %2, %0;" : "+l"(d) : "l"(a), "l"(b))
#define LDSV2(s0, s1, ad) asm volatile("ld.shared.v2.b64 {%0, %1}, [%2];" \
                                       : "=l"(s0), "=l"(s1) : "r"(ad))

// ---------------------------------------------------------------------------
__global__ void fold_w_kernel(const float* __restrict__ w) {
    int t = blockIdx.x * blockDim.x + threadIdx.x;
    if (t < COUT * 49) {
        int c = t / 49, kk = t % 49;
        const float* p = w + c * 147;
        g_wsum[t] = p[kk] + p[49 + kk] + p[98 + kk];
    }
}

// ---- spectrogram: one thread per (b, frame, freq-bin) ----------------------
__global__ void spec_kernel(const float* __restrict__ x, int B) {
    int t = blockIdx.x * blockDim.x + threadIdx.x;
    if (t >= B * NFR * NFQ) return;
    int k  = t % NFQ;
    int r  = t / NFQ;
    int fr = r % NFR;
    int b  = r / NFR;

    const float* s = x + b * SIGLEN + fr * STEP;
    float v[8];
    float mean = 0.f;
#pragma unroll
    for (int n = 0; n < 8; n++) { v[n] = s[n]; mean += v[n]; }
    mean *= 0.125f;
    float re = 0.f, im = 0.f;
#pragma unroll
    for (int n = 1; n < 8; n++) {
        float f = v[n] - mean;
        float sn, cs;
        sincospif((float)(k * n) * (1.0f / 32.0f), &sn, &cs);
        re += f * cs;
        im -= f * sn;
    }
    const float SCALE = sqrtf(1.0f / (178.0f * 7.0f));
    g_spec[b * (NFQ * NFR) + k * NFR + fr] = sqrtf(re * re + im * im) * SCALE;
}

// ---- stage A: Phi[j][qt][ky][c] = sum_kx wsum[c,ky,kx] * bweight -----------
__global__ void phi_kernel() {
    int t = blockIdx.x * blockDim.x + threadIdx.x;
    if (t >= 89 * 4 * 7 * 64) return;
    int c  = t & 63;
    int u  = t >> 6;
    int ky = u % 7;  u /= 7;
    int qt = u % 4;
    int j  = u / 4;
    int q  = q0f(j) + qt;
    float a = 0.f;
#pragma unroll
    for (int kx = 0; kx < 7; kx++)
        a += g_wsum[c * 49 + ky * 7 + kx] * bweight(2 * j - 3 + kx, q);
    g_phi[((j * 4 + qt) * 7 + ky) * 64 + c] = a;
}

// ---- stage B: Theta[r][j][pt*4+qt][c] = sum_ky aweight * Phi ---------------
__global__ void theta_kernel() {
    int j = blockIdx.x, r = blockIdx.y;
    int tid = threadIdx.x;
    int c = tid & 63, qt = tid >> 6;
    int p0 = p0f(r);

    float f[7];
#pragma unroll
    for (int ky = 0; ky < 7; ky++)
        f[ky] = g_phi[((j * 4 + qt) * 7 + ky) * 64 + c];

    float th[4] = {0.f, 0.f, 0.f, 0.f};
#pragma unroll
    for (int ky = 0; ky < 7; ky++) {
        int y = 2 * r - 3 + ky;
        if (y < 0 || y >= 178) continue;
        float sy = fminf(fmaxf((y + 0.5f) * (33.0f / 178.0f) - 0.5f, 0.f), 32.f);
        int y0 = (int)sy; float fy = sy - (float)y0; int y1 = min(y0 + 1, 32);
#pragma unroll
        for (int pt = 0; pt < 4; pt++) {
            int p = p0 + pt;
            float w = (p == y0) ? (1.f - fy) : 0.f;
            if (p == y1) w += fy;
            th[pt] += w * f[ky];
        }
    }
#pragma unroll
    for (int pt = 0; pt < 4; pt++)
        g_theta[((r * 89 + j) * 16 + pt * 4 + qt) * 64 + c] = th[pt];
}

// ---- main: 16-tap sparse op, batched x16, FFMA2, fused relu+GAP ------------
__global__ void __launch_bounds__(256)
tap_kernel(const float* __restrict__ bias, int B) {
    extern __shared__ float s[];          // [NFQ*NFR][NB] = 90816 B
    int tid = threadIdx.x;
    int b0  = blockIdx.z * NB;

    for (int i = tid; i < NFQ * NFR * NB; i += 256) {
        int nb = i / (NFQ * NFR);
        int pq = i - nb * (NFQ * NFR);
        int b  = b0 + nb;
        s[pq * NB + nb] = (b < B) ? g_spec[b * (NFQ * NFR) + pq] : 0.f;
    }
    __syncthreads();

    unsigned sbase;
    asm("{ .reg .u64 t; cvta.to.shared.u64 t, %1; cvt.u32.u64 %0, t; }"
        : "=r"(sbase) : "l"(s));

    int c = tid & 63, jql = tid >> 6;
    int jbase = (blockIdx.x * 4 + jql) * 4;
    int q0b = min(q0raw(jbase), 37);

    int  qoff[4], jmin[4];
    bool jv[4];
#pragma unroll
    for (int jj = 0; jj < 4; jj++) {
        int j = jbase + jj;
        jv[jj]   = (j < CONV_OUT);
        jmin[jj] = jv[jj] ? j : 88;
        qoff[jj] = q0f(jmin[jj]) - q0b;
    }

    float bc = bias[c];
    unsigned long long bc2; PACK2(bc2, bc);

    float acc[NB];
#pragma unroll
    for (int i = 0; i < NB; i++) acc[i] = 0.f;

    int rlo = (CONV_OUT * (int)blockIdx.y) / 8;
    int rhi = (CONV_OUT * ((int)blockIdx.y + 1)) / 8;

    for (int r = rlo; r < rhi; ++r) {
        int p0 = p0f(r);
        const float* trow = g_theta + (size_t)(r * 89) * 1024;
        unsigned srow0 = sbase + (unsigned)((p0 * NFR + q0b) * NB) * 4u;

#pragma unroll
        for (int jj = 0; jj < 4; jj++) {
            const float* th = trow + jmin[jj] * 1024 + c;
            unsigned sa = srow0 + (unsigned)(qoff[jj] * NB) * 4u;
            unsigned long long d0 = bc2, d1 = bc2, d2 = bc2, d3 = bc2,
                               d4 = bc2, d5 = bc2, d6 = bc2, d7 = bc2;
#pragma unroll
            for (int pt = 0; pt < 4; pt++) {
                unsigned long long T[4];
                {
                    float t0 = th[(pt * 4 + 0) * 64];
                    float t1 = th[(pt * 4 + 1) * 64];
                    float t2 = th[(pt * 4 + 2) * 64];
                    float t3 = th[(pt * 4 + 3) * 64];
                    PACK2(T[0], t0); PACK2(T[1], t1);
                    PACK2(T[2], t2); PACK2(T[3], t3);
                }
                unsigned a0 = sa + (unsigned)(pt * NFR * NB) * 4u;
#pragma unroll
                for (int qt = 0; qt < 4; qt++) {
                    unsigned ad = a0 + (unsigned)(qt * NB) * 4u;
                    unsigned long long s0, s1, s2, s3, s4, s5, s6, s7;
                    LDSV2(s0, s1, ad);
                    LDSV2(s2, s3, ad + 16u);
                    LDSV2(s4, s5, ad + 32u);
                    LDSV2(s6, s7, ad + 48u);
                    FFMA2(d0, T[qt], s0); FFMA2(d1, T[qt], s1);
                    FFMA2(d2, T[qt], s2); FFMA2(d3, T[qt], s3);
                    FFMA2(d4, T[qt], s4); FFMA2(d5, T[qt], s5);
                    FFMA2(d6, T[qt], s6); FFMA2(d7, T[qt], s7);
                }
            }
            if (jv[jj]) {
                float lo, hi;
                UNPACK2(lo, hi, d0); acc[0]  += fmaxf(lo, 0.f); acc[1]  += fmaxf(hi, 0.f);
                UNPACK2(lo, hi, d1); acc[2]  += fmaxf(lo, 0.f); acc[3]  += fmaxf(hi, 0.f);
                UNPACK2(lo, hi, d2); acc[4]  += fmaxf(lo, 0.f); acc[5]  += fmaxf(hi, 0.f);
                UNPACK2(lo, hi, d3); acc[6]  += fmaxf(lo, 0.f); acc[7]  += fmaxf(hi, 0.f);
                UNPACK2(lo, hi, d4); acc[8]  += fmaxf(lo, 0.f); acc[9]  += fmaxf(hi, 0.f);
                UNPACK2(lo, hi, d5); acc[10] += fmaxf(lo, 0.f); acc[11] += fmaxf(hi, 0.f);
                UNPACK2(lo, hi, d6); acc[12] += fmaxf(lo, 0.f); acc[13] += fmaxf(hi, 0.f);
                UNPACK2(lo, hi, d7); acc[14] += fmaxf(lo, 0.f); acc[15] += fmaxf(hi, 0.f);
            }
        }
    }

    // block reduce over the 4 jql groups
    __syncthreads();
#pragma unroll
    for (int i = 0; i < NB; i++) s[tid * NB + i] = acc[i];
    __syncthreads();

    int part = blockIdx.y * 6 + blockIdx.x;
    for (int i = tid; i < 64 * NB; i += 256) {
        int c2 = i >> 4, nb = i & 15;
        float v = s[(c2) * NB + nb] + s[(64 + c2) * NB + nb]
                + s[(128 + c2) * NB + nb] + s[(192 + c2) * NB + nb];
        int b = b0 + nb;
        if (b < B) g_part[(b * COUT + c2) * NPARTS + part] = v;
    }
}

// ---- final: GAP mean + FC --------------------------------------------------
__global__ void fc_kernel(const float* __restrict__ fw,
                          const float* __restrict__ fb,
                          float* __restrict__ out, int B) {
    __shared__ float sm[COUT];
    int b = blockIdx.x;
    int tid = threadIdx.x;
    float sum = 0.f;
    const float* p = g_part + (b * COUT + tid) * NPARTS;
#pragma unroll
    for (int k = 0; k < NPARTS; k++) sum += p[k];
    sm[tid] = sum;
    __syncthreads();
    if (tid < 5) {
        const float inv = 1.0f / (float)(CONV_OUT * CONV_OUT);
        float accv = fb[tid];
#pragma unroll 8
        for (int c2 = 0; c2 < COUT; c2++)
            accv = fmaf(sm[c2] * inv, fw[tid * 64 + c2], accv);
        out[b * 5 + tid] = accv;
    }
}

// ---------------------------------------------------------------------------
extern "C" void kernel_launch(void* const* d_in, const int* in_sizes, int n_in,
                              void* d_out, int out_size) {
    const float* x      = (const float*)d_in[0];
    const float* conv_w = (const float*)d_in[1];
    const float* conv_b = (const float*)d_in[2];
    const float* fc_w   = (const float*)d_in[3];
    const float* fc_b   = (const float*)d_in[4];
    float*       out    = (float*)d_out;

    int B = in_sizes[0] / SIGLEN;
    if (B > BMAX) B = BMAX;

    cudaFuncSetAttribute(tap_kernel,
                         cudaFuncAttributeMaxDynamicSharedMemorySize, 92160);

    fold_w_kernel<<<(COUT * 49 + 255) / 256, 256>>>(conv_w);

    int nspec = B * NFR * NFQ;
    spec_kernel<<<(nspec + 255) / 256, 256>>>(x, B);

    phi_kernel<<<(89 * 4 * 7 * 64 + 255) / 256, 256>>>();

    dim3 tgrid(89, 89);
    theta_kernel<<<tgrid, 256>>>();

    int chunks = (B + NB - 1) / NB;
    dim3 mgrid(6, 8, chunks);
    tap_kernel<<<mgrid, 256, NFQ * NFR * NB * sizeof(float)>>>(conv_b, B);

    fc_kernel<<<B, COUT>>>(fc_w, fc_b, out, B);
}